// round 1
// baseline (speedup 1.0000x reference)
#include <cuda_runtime.h>
#include <math.h>

// Problem shape (fixed)
#define BB 256
#define TT 256
#define CC 512
#define HH 64

// Scratch for projections (device globals: no allocation allowed)
__device__ float g_q[BB * TT * HH];
__device__ float g_k[BB * TT * HH];
__device__ float g_v[BB * TT * HH];

// ---------------------------------------------------------------------------
// Projection GEMM: Co[M,N] = A[M,K] @ W[K,N]; M=65536, K=512, N=64.
// Tile 64x64, BK=32, 256 threads, 4x4 per-thread micro-tile.
// mode: 0 -> g_q, 1 -> g_k, 2 -> g_v
// ---------------------------------------------------------------------------
__global__ __launch_bounds__(256) void proj_kernel(const float* __restrict__ A,
                                                   const float* __restrict__ W,
                                                   int mode) {
    __shared__ float As[32][68];  // [k][m], padded (68 keeps float4 alignment + spreads banks)
    __shared__ float Bs[32][64];  // [k][n]

    float* __restrict__ Co = (mode == 0) ? g_q : (mode == 1) ? g_k : g_v;

    const int tid = threadIdx.x;
    const int tx = tid & 15;       // 0..15 -> n
    const int ty = tid >> 4;       // 0..15 -> m
    const int m0 = blockIdx.x * 64;

    float acc[4][4];
#pragma unroll
    for (int i = 0; i < 4; i++)
#pragma unroll
        for (int j = 0; j < 4; j++) acc[i][j] = 0.0f;

    for (int k0 = 0; k0 < CC; k0 += 32) {
        // Load A tile: 64 rows x 32 cols = 512 float4; 2 per thread.
#pragma unroll
        for (int l = 0; l < 2; l++) {
            int f = tid + l * 256;
            int r = f >> 3;               // 0..63
            int c4 = (f & 7) << 2;        // 0..28
            float4 a = *(const float4*)&A[(size_t)(m0 + r) * CC + k0 + c4];
            As[c4 + 0][r] = a.x;
            As[c4 + 1][r] = a.y;
            As[c4 + 2][r] = a.z;
            As[c4 + 3][r] = a.w;
            // W tile: 32 rows x 64 cols = 512 float4; 2 per thread.
            int rb = f >> 4;              // 0..31
            int cb = (f & 15) << 2;       // 0..60
            *(float4*)&Bs[rb][cb] = *(const float4*)&W[(size_t)(k0 + rb) * HH + cb];
        }
        __syncthreads();

#pragma unroll
        for (int k = 0; k < 32; k++) {
            float4 a4 = *(float4*)&As[k][ty * 4];
            float4 b4 = *(float4*)&Bs[k][tx * 4];
            float av[4] = {a4.x, a4.y, a4.z, a4.w};
            float bv[4] = {b4.x, b4.y, b4.z, b4.w};
#pragma unroll
            for (int i = 0; i < 4; i++)
#pragma unroll
                for (int j = 0; j < 4; j++) acc[i][j] = fmaf(av[i], bv[j], acc[i][j]);
        }
        __syncthreads();
    }

#pragma unroll
    for (int i = 0; i < 4; i++) {
        float4 o = make_float4(acc[i][0], acc[i][1], acc[i][2], acc[i][3]);
        *(float4*)&Co[(size_t)(m0 + ty * 4 + i) * HH + tx * 4] = o;
    }
}

// ---------------------------------------------------------------------------
// Attention: one block per batch. 512 threads = 16 warps.
// K staged in smem with 68-float row pitch (conflict-free strided float4 reads),
// V with 64-float pitch. Each warp processes 2 query rows (t0, t0+16) at once.
// ---------------------------------------------------------------------------
#define KPITCH 68
#define NWARP 16

__global__ __launch_bounds__(512) void attn_kernel(float* __restrict__ out) {
    extern __shared__ float sm[];
    float* Ks = sm;                        // 256*68
    float* Vs = Ks + TT * KPITCH;          // 256*64
    float* ws = Vs + TT * HH;              // NWARP*2*256
    float* qs = ws + NWARP * 2 * TT;       // NWARP*2*64

    const int b = blockIdx.x;
    const int tid = threadIdx.x;
    const int w = tid >> 5;
    const int lane = tid & 31;

    const float* __restrict__ Kg = g_k + (size_t)b * TT * HH;
    const float* __restrict__ Vg = g_v + (size_t)b * TT * HH;
    const float* __restrict__ Qg = g_q + (size_t)b * TT * HH;

    // Stage K and V: 256 rows x 16 float4 each.
    for (int i = tid; i < TT * 16; i += 512) {
        int r = i >> 4;
        int c4 = (i & 15) << 2;
        *(float4*)&Ks[r * KPITCH + c4] = *(const float4*)&Kg[r * HH + c4];
        *(float4*)&Vs[r * HH + c4] = *(const float4*)&Vg[r * HH + c4];
    }
    __syncthreads();

    float* ws0 = ws + w * 2 * TT;
    float* ws1 = ws0 + TT;
    float* qs0 = qs + w * 2 * HH;
    float* qs1 = qs0 + HH;

    const float scale = 0.125f;  // 1/sqrt(64)

    for (int it = 0; it < TT / (2 * NWARP); it++) {  // 8 sweeps
        const int t0 = it * 32 + w;       // (t mod 32) in 0..15
        const int t1 = t0 + NWARP;        // (t mod 32) in 16..31

        __syncwarp();
        // Load the two query rows into per-warp smem.
        qs0[lane] = Qg[t0 * HH + lane];
        qs0[lane + 32] = Qg[t0 * HH + lane + 32];
        qs1[lane] = Qg[t1 * HH + lane];
        qs1[lane + 32] = Qg[t1 * HH + lane + 32];
        __syncwarp();

        const int jmax = t1 >> 5;  // highest 32-key group touched

        float acc0[8], acc1[8];
#pragma unroll
        for (int j = 0; j < 8; j++) { acc0[j] = 0.0f; acc1[j] = 0.0f; }

        // Scores: both rows share each K read.
#pragma unroll 4
        for (int h = 0; h < HH; h += 4) {
            float4 q0 = *(float4*)&qs0[h];
            float4 q1 = *(float4*)&qs1[h];
#pragma unroll
            for (int j = 0; j < 8; j++) {
                if (j <= jmax) {
                    int s = lane + (j << 5);
                    float4 k4 = *(float4*)&Ks[s * KPITCH + h];
                    acc0[j] = fmaf(q0.x, k4.x, acc0[j]);
                    acc0[j] = fmaf(q0.y, k4.y, acc0[j]);
                    acc0[j] = fmaf(q0.z, k4.z, acc0[j]);
                    acc0[j] = fmaf(q0.w, k4.w, acc0[j]);
                    acc1[j] = fmaf(q1.x, k4.x, acc1[j]);
                    acc1[j] = fmaf(q1.y, k4.y, acc1[j]);
                    acc1[j] = fmaf(q1.z, k4.z, acc1[j]);
                    acc1[j] = fmaf(q1.w, k4.w, acc1[j]);
                }
            }
        }

        // Softmax (warp-parallel over s = lane + 32j).
        const float NEG = -1e30f;
        float m0 = NEG, m1 = NEG;
#pragma unroll
        for (int j = 0; j < 8; j++) {
            int s = lane + (j << 5);
            float v0 = (j <= jmax && s <= t0) ? acc0[j] * scale : NEG;
            float v1 = (j <= jmax && s <= t1) ? acc1[j] * scale : NEG;
            acc0[j] = v0; acc1[j] = v1;
            m0 = fmaxf(m0, v0); m1 = fmaxf(m1, v1);
        }
#pragma unroll
        for (int off = 16; off > 0; off >>= 1) {
            m0 = fmaxf(m0, __shfl_xor_sync(0xffffffffu, m0, off));
            m1 = fmaxf(m1, __shfl_xor_sync(0xffffffffu, m1, off));
        }
        float sum0 = 0.0f, sum1 = 0.0f;
#pragma unroll
        for (int j = 0; j < 8; j++) {
            float p0 = (acc0[j] > NEG * 0.5f) ? __expf(acc0[j] - m0) : 0.0f;
            float p1 = (acc1[j] > NEG * 0.5f) ? __expf(acc1[j] - m1) : 0.0f;
            acc0[j] = p0; acc1[j] = p1;
            sum0 += p0; sum1 += p1;
        }
#pragma unroll
        for (int off = 16; off > 0; off >>= 1) {
            sum0 += __shfl_xor_sync(0xffffffffu, sum0, off);
            sum1 += __shfl_xor_sync(0xffffffffu, sum1, off);
        }
        float inv0 = __frcp_rn(sum0);
        float inv1 = __frcp_rn(sum1);
#pragma unroll
        for (int j = 0; j < 8; j++) {
            if (j <= jmax) {
                int s = lane + (j << 5);
                ws0[s] = acc0[j] * inv0;  // masked slots carry 0
                ws1[s] = acc1[j] * inv1;
            }
        }
        __syncwarp();

        // PV: both rows share each V read. Lane owns h = lane, lane+32.
        float o0a = 0.0f, o0b = 0.0f, o1a = 0.0f, o1b = 0.0f;
        for (int s = 0; s <= t1; s++) {
            float p0 = ws0[s];  // zero for s > t0
            float p1 = ws1[s];
            float va = Vs[s * HH + lane];
            float vb = Vs[s * HH + lane + 32];
            o0a = fmaf(p0, va, o0a);
            o0b = fmaf(p0, vb, o0b);
            o1a = fmaf(p1, va, o1a);
            o1b = fmaf(p1, vb, o1b);
        }
        float* ob = out + (size_t)b * TT * HH;
        ob[t0 * HH + lane] = o0a;
        ob[t0 * HH + lane + 32] = o0b;
        ob[t1 * HH + lane] = o1a;
        ob[t1 * HH + lane + 32] = o1b;
    }
}

// ---------------------------------------------------------------------------
extern "C" void kernel_launch(void* const* d_in, const int* in_sizes, int n_in,
                              void* d_out, int out_size) {
    const float* x = (const float*)d_in[0];
    const float* y = (const float*)d_in[1];
    const float* Wq = (const float*)d_in[2];
    const float* Wk = (const float*)d_in[3];
    const float* Wv = (const float*)d_in[4];
    float* out = (float*)d_out;

    // Projections: q = x@Wq, k = y@Wk, v = y@Wv  (M=65536 -> 1024 tiles of 64)
    proj_kernel<<<1024, 256>>>(x, Wq, 0);
    proj_kernel<<<1024, 256>>>(y, Wk, 1);
    proj_kernel<<<1024, 256>>>(y, Wv, 2);

    // Attention
    size_t smem = (size_t)(TT * KPITCH + TT * HH + NWARP * 2 * TT + NWARP * 2 * HH) * sizeof(float);
    static bool attr_set = false;
    if (!attr_set) {
        cudaFuncSetAttribute(attn_kernel, cudaFuncAttributeMaxDynamicSharedMemorySize, (int)smem);
        attr_set = true;
    }
    attn_kernel<<<BB, 512, smem>>>(out);
}

// round 2
// speedup vs baseline: 1.7200x; 1.7200x over previous
#include <cuda_runtime.h>
#include <math.h>

// Problem shape (fixed)
#define BB 256
#define TT 256
#define CC 512
#define HH 64

// Scratch for projections (device globals: no allocation allowed)
__device__ float g_q[BB * TT * HH];
__device__ float g_k[BB * TT * HH];
__device__ float g_v[BB * TT * HH];

__device__ __forceinline__ unsigned f2tf32(float f) {
    unsigned r;
    asm("cvt.rna.tf32.f32 %0, %1;" : "=r"(r) : "f"(f));
    return r;
}

__device__ __forceinline__ void mma_tf32(float c[4], const unsigned a[4], const unsigned b[2]) {
    asm volatile(
        "mma.sync.aligned.m16n8k8.row.col.f32.tf32.tf32.f32 "
        "{%0,%1,%2,%3}, {%4,%5,%6,%7}, {%8,%9}, {%0,%1,%2,%3};\n"
        : "+f"(c[0]), "+f"(c[1]), "+f"(c[2]), "+f"(c[3])
        : "r"(a[0]), "r"(a[1]), "r"(a[2]), "r"(a[3]), "r"(b[0]), "r"(b[1]));
}

// ---------------------------------------------------------------------------
// Projection GEMM via tf32 mma.sync: C[M,BN] = A[M,512] @ [W0|W1].
// Block tile 128 x BN, BK=32, 256 threads = 8 warps (4 in M x 2 in N).
// BN=64  -> single output (C0), warp tile 32x32.
// BN=128 -> fused k|v   (C0,C1), warp tile 32x64.
// ---------------------------------------------------------------------------
template <int BN>
__global__ __launch_bounds__(256) void proj_mma_kernel(const float* __restrict__ A,
                                                       const float* __restrict__ W0,
                                                       const float* __restrict__ W1,
                                                       float* __restrict__ C0,
                                                       float* __restrict__ C1) {
    constexpr int APITCH = 36;       // bank = (4g + tig) % 32 -> conflict-free frags
    constexpr int BPITCH = BN + 4;   // (BN+4)%32 == 4 -> conflict-free frags
    constexpr int WN = BN / 2;       // warp covers WN columns
    constexpr int NT = WN / 8;       // n-tiles per warp (4 or 8)

    __shared__ unsigned As[128][APITCH];
    __shared__ unsigned Bs[32][BPITCH];

    const int tid = threadIdx.x;
    const int wid = tid >> 5;
    const int lane = tid & 31;
    const int wm = wid & 3;          // warp row (0..3) -> 32 rows
    const int wn = wid >> 2;         // warp col (0..1) -> WN cols
    const int g = lane >> 2;         // 0..7
    const int tig = lane & 3;        // 0..3
    const int m0 = blockIdx.x * 128;

    float c[2][NT][4];
#pragma unroll
    for (int mt = 0; mt < 2; mt++)
#pragma unroll
        for (int nt = 0; nt < NT; nt++)
#pragma unroll
            for (int i = 0; i < 4; i++) c[mt][nt][i] = 0.0f;

    for (int k0 = 0; k0 < CC; k0 += 32) {
        // --- A tile: 128 x 32 floats = 1024 float4; 4 per thread. cvt at store.
#pragma unroll
        for (int l = 0; l < 4; l++) {
            int idx = tid + l * 256;
            int r = idx >> 3;            // 0..127
            int c4 = (idx & 7) << 2;     // 0..28
            float4 a = *(const float4*)&A[(size_t)(m0 + r) * CC + k0 + c4];
            As[r][c4 + 0] = f2tf32(a.x);
            As[r][c4 + 1] = f2tf32(a.y);
            As[r][c4 + 2] = f2tf32(a.z);
            As[r][c4 + 3] = f2tf32(a.w);
        }
        // --- B tile: 32 x BN floats. W0 -> cols [0,64), W1 -> cols [64,128).
        constexpr int BV = (32 * BN) / 4;       // float4 count (512 or 1024)
#pragma unroll
        for (int l = 0; l < BV / 256; l++) {
            int idx = tid + l * 256;
            int r = idx / (BN / 4);             // k row 0..31
            int cc = (idx % (BN / 4)) << 2;     // col 0..BN-4
            const float* Wsrc = (cc < 64) ? W0 : W1;
            int wc = (cc < 64) ? cc : cc - 64;
            float4 b = *(const float4*)&Wsrc[(size_t)(k0 + r) * HH + wc];
            Bs[r][cc + 0] = f2tf32(b.x);
            Bs[r][cc + 1] = f2tf32(b.y);
            Bs[r][cc + 2] = f2tf32(b.z);
            Bs[r][cc + 3] = f2tf32(b.w);
        }
        __syncthreads();

#pragma unroll
        for (int ks = 0; ks < 4; ks++) {
            const int kb = ks * 8;
            unsigned af[2][4];
#pragma unroll
            for (int mt = 0; mt < 2; mt++) {
                int r = wm * 32 + mt * 16;
                af[mt][0] = As[r + g][kb + tig];
                af[mt][1] = As[r + g + 8][kb + tig];
                af[mt][2] = As[r + g][kb + tig + 4];
                af[mt][3] = As[r + g + 8][kb + tig + 4];
            }
            unsigned bf[NT][2];
#pragma unroll
            for (int nt = 0; nt < NT; nt++) {
                int cb = wn * WN + nt * 8;
                bf[nt][0] = Bs[kb + tig][cb + g];
                bf[nt][1] = Bs[kb + tig + 4][cb + g];
            }
#pragma unroll
            for (int mt = 0; mt < 2; mt++)
#pragma unroll
                for (int nt = 0; nt < NT; nt++) mma_tf32(c[mt][nt], af[mt], bf[nt]);
        }
        __syncthreads();
    }

    // Epilogue: c0/c1 are (row g, cols 2tig,2tig+1); c2/c3 at row g+8.
#pragma unroll
    for (int mt = 0; mt < 2; mt++) {
#pragma unroll
        for (int nt = 0; nt < NT; nt++) {
            int gcol = wn * WN + nt * 8 + 2 * tig;   // 0..BN-2
            float* dst;
            int col;
            if (BN == 64) { dst = C0; col = gcol; }
            else { dst = (gcol < 64) ? C0 : C1; col = (gcol < 64) ? gcol : gcol - 64; }
            int row = m0 + wm * 32 + mt * 16 + g;
            *(float2*)&dst[(size_t)row * HH + col] = make_float2(c[mt][nt][0], c[mt][nt][1]);
            *(float2*)&dst[(size_t)(row + 8) * HH + col] = make_float2(c[mt][nt][2], c[mt][nt][3]);
        }
    }
}

// ---------------------------------------------------------------------------
// Attention: one block per batch. 512 threads = 16 warps. (unchanged from R0)
// ---------------------------------------------------------------------------
#define KPITCH 68
#define NWARP 16

__global__ __launch_bounds__(512) void attn_kernel(float* __restrict__ out) {
    extern __shared__ float sm[];
    float* Ks = sm;                        // 256*68
    float* Vs = Ks + TT * KPITCH;          // 256*64
    float* ws = Vs + TT * HH;              // NWARP*2*256
    float* qs = ws + NWARP * 2 * TT;       // NWARP*2*64

    const int b = blockIdx.x;
    const int tid = threadIdx.x;
    const int w = tid >> 5;
    const int lane = tid & 31;

    const float* __restrict__ Kg = g_k + (size_t)b * TT * HH;
    const float* __restrict__ Vg = g_v + (size_t)b * TT * HH;
    const float* __restrict__ Qg = g_q + (size_t)b * TT * HH;

    for (int i = tid; i < TT * 16; i += 512) {
        int r = i >> 4;
        int c4 = (i & 15) << 2;
        *(float4*)&Ks[r * KPITCH + c4] = *(const float4*)&Kg[r * HH + c4];
        *(float4*)&Vs[r * HH + c4] = *(const float4*)&Vg[r * HH + c4];
    }
    __syncthreads();

    float* ws0 = ws + w * 2 * TT;
    float* ws1 = ws0 + TT;
    float* qs0 = qs + w * 2 * HH;
    float* qs1 = qs0 + HH;

    const float scale = 0.125f;

    for (int it = 0; it < TT / (2 * NWARP); it++) {
        const int t0 = it * 32 + w;
        const int t1 = t0 + NWARP;

        __syncwarp();
        qs0[lane] = Qg[t0 * HH + lane];
        qs0[lane + 32] = Qg[t0 * HH + lane + 32];
        qs1[lane] = Qg[t1 * HH + lane];
        qs1[lane + 32] = Qg[t1 * HH + lane + 32];
        __syncwarp();

        const int jmax = t1 >> 5;

        float acc0[8], acc1[8];
#pragma unroll
        for (int j = 0; j < 8; j++) { acc0[j] = 0.0f; acc1[j] = 0.0f; }

#pragma unroll 4
        for (int h = 0; h < HH; h += 4) {
            float4 q0 = *(float4*)&qs0[h];
            float4 q1 = *(float4*)&qs1[h];
#pragma unroll
            for (int j = 0; j < 8; j++) {
                if (j <= jmax) {
                    int s = lane + (j << 5);
                    float4 k4 = *(float4*)&Ks[s * KPITCH + h];
                    acc0[j] = fmaf(q0.x, k4.x, acc0[j]);
                    acc0[j] = fmaf(q0.y, k4.y, acc0[j]);
                    acc0[j] = fmaf(q0.z, k4.z, acc0[j]);
                    acc0[j] = fmaf(q0.w, k4.w, acc0[j]);
                    acc1[j] = fmaf(q1.x, k4.x, acc1[j]);
                    acc1[j] = fmaf(q1.y, k4.y, acc1[j]);
                    acc1[j] = fmaf(q1.z, k4.z, acc1[j]);
                    acc1[j] = fmaf(q1.w, k4.w, acc1[j]);
                }
            }
        }

        const float NEG = -1e30f;
        float m0 = NEG, m1 = NEG;
#pragma unroll
        for (int j = 0; j < 8; j++) {
            int s = lane + (j << 5);
            float v0 = (j <= jmax && s <= t0) ? acc0[j] * scale : NEG;
            float v1 = (j <= jmax && s <= t1) ? acc1[j] * scale : NEG;
            acc0[j] = v0; acc1[j] = v1;
            m0 = fmaxf(m0, v0); m1 = fmaxf(m1, v1);
        }
#pragma unroll
        for (int off = 16; off > 0; off >>= 1) {
            m0 = fmaxf(m0, __shfl_xor_sync(0xffffffffu, m0, off));
            m1 = fmaxf(m1, __shfl_xor_sync(0xffffffffu, m1, off));
        }
        float sum0 = 0.0f, sum1 = 0.0f;
#pragma unroll
        for (int j = 0; j < 8; j++) {
            float p0 = (acc0[j] > NEG * 0.5f) ? __expf(acc0[j] - m0) : 0.0f;
            float p1 = (acc1[j] > NEG * 0.5f) ? __expf(acc1[j] - m1) : 0.0f;
            acc0[j] = p0; acc1[j] = p1;
            sum0 += p0; sum1 += p1;
        }
#pragma unroll
        for (int off = 16; off > 0; off >>= 1) {
            sum0 += __shfl_xor_sync(0xffffffffu, sum0, off);
            sum1 += __shfl_xor_sync(0xffffffffu, sum1, off);
        }
        float inv0 = __frcp_rn(sum0);
        float inv1 = __frcp_rn(sum1);
#pragma unroll
        for (int j = 0; j < 8; j++) {
            if (j <= jmax) {
                int s = lane + (j << 5);
                ws0[s] = acc0[j] * inv0;
                ws1[s] = acc1[j] * inv1;
            }
        }
        __syncwarp();

        float o0a = 0.0f, o0b = 0.0f, o1a = 0.0f, o1b = 0.0f;
        for (int s = 0; s <= t1; s++) {
            float p0 = ws0[s];
            float p1 = ws1[s];
            float va = Vs[s * HH + lane];
            float vb = Vs[s * HH + lane + 32];
            o0a = fmaf(p0, va, o0a);
            o0b = fmaf(p0, vb, o0b);
            o1a = fmaf(p1, va, o1a);
            o1b = fmaf(p1, vb, o1b);
        }
        float* ob = out + (size_t)b * TT * HH;
        ob[t0 * HH + lane] = o0a;
        ob[t0 * HH + lane + 32] = o0b;
        ob[t1 * HH + lane] = o1a;
        ob[t1 * HH + lane + 32] = o1b;
    }
}

// ---------------------------------------------------------------------------
extern "C" void kernel_launch(void* const* d_in, const int* in_sizes, int n_in,
                              void* d_out, int out_size) {
    const float* x = (const float*)d_in[0];
    const float* y = (const float*)d_in[1];
    const float* Wq = (const float*)d_in[2];
    const float* Wk = (const float*)d_in[3];
    const float* Wv = (const float*)d_in[4];
    float* out = (float*)d_out;

    float* gq;  cudaGetSymbolAddress((void**)&gq, g_q);
    float* gk;  cudaGetSymbolAddress((void**)&gk, g_k);
    float* gv;  cudaGetSymbolAddress((void**)&gv, g_v);

    // q = x @ Wq  (N=64); [k|v] = y @ [Wk|Wv]  (N=128, y read once)
    proj_mma_kernel<64><<<512, 256>>>(x, Wq, Wq, gq, gq);
    proj_mma_kernel<128><<<512, 256>>>(y, Wk, Wv, gk, gv);

    // Attention
    size_t smem = (size_t)(TT * KPITCH + TT * HH + NWARP * 2 * TT + NWARP * 2 * HH) * sizeof(float);
    static bool attr_set = false;
    if (!attr_set) {
        cudaFuncSetAttribute(attn_kernel, cudaFuncAttributeMaxDynamicSharedMemorySize, (int)smem);
        attr_set = true;
    }
    attn_kernel<<<BB, 512, smem>>>(out);
}

// round 3
// speedup vs baseline: 2.0752x; 1.2065x over previous
#include <cuda_runtime.h>
#include <math.h>
#include <stdint.h>

// Problem shape (fixed)
#define BB 256
#define TT 256
#define CC 512
#define HH 64

// Scratch for projections (device globals: no allocation allowed)
__device__ float g_q[BB * TT * HH];
__device__ float g_k[BB * TT * HH];
__device__ float g_v[BB * TT * HH];

__device__ __forceinline__ unsigned f2tf32(float f) {
    unsigned r;
    asm("cvt.rna.tf32.f32 %0, %1;" : "=r"(r) : "f"(f));
    return r;
}

__device__ __forceinline__ void mma_tf32(float c[4], const unsigned a[4], const unsigned b[2]) {
    asm volatile(
        "mma.sync.aligned.m16n8k8.row.col.f32.tf32.tf32.f32 "
        "{%0,%1,%2,%3}, {%4,%5,%6,%7}, {%8,%9}, {%0,%1,%2,%3};\n"
        : "+f"(c[0]), "+f"(c[1]), "+f"(c[2]), "+f"(c[3])
        : "r"(a[0]), "r"(a[1]), "r"(a[2]), "r"(a[3]), "r"(b[0]), "r"(b[1]));
}

__device__ __forceinline__ void cp_async16(void* smem_dst, const void* gmem_src) {
    uint32_t d = (uint32_t)__cvta_generic_to_shared(smem_dst);
    asm volatile("cp.async.cg.shared.global [%0], [%1], 16;\n" :: "r"(d), "l"(gmem_src));
}
__device__ __forceinline__ void cp_commit() { asm volatile("cp.async.commit_group;\n"); }

// ---------------------------------------------------------------------------
// Projection GEMM via tf32 mma.sync + cp.async 2-stage pipeline.
// C[M,BN] = A[M,512] @ [W0|W1]. Block tile 128 x BN, BK=32, 256 threads.
// ---------------------------------------------------------------------------
template <int BN>
__global__ __launch_bounds__(256) void proj_mma_kernel(const float* __restrict__ A,
                                                       const float* __restrict__ W0,
                                                       const float* __restrict__ W1,
                                                       float* __restrict__ C0,
                                                       float* __restrict__ C1) {
    constexpr int APITCH = 36;       // bank = (4g + tig) % 32 -> conflict-free frags
    constexpr int BPITCH = BN + 4;   // (BN+4)%32 == 4 -> conflict-free-ish frags
    constexpr int WN = BN / 2;
    constexpr int NT = WN / 8;
    constexpr int NK = CC / 32;      // 16 k-tiles

    extern __shared__ float smraw[];
    float* Asf = smraw;                        // [2][128][APITCH]
    float* Bsf = smraw + 2 * 128 * APITCH;     // [2][32][BPITCH]

    const int tid = threadIdx.x;
    const int wid = tid >> 5;
    const int lane = tid & 31;
    const int wm = wid & 3;
    const int wn = wid >> 2;
    const int g = lane >> 2;
    const int tig = lane & 3;
    const int m0 = blockIdx.x * 128;

    auto load_tile = [&](int st, int k0) {
        float* As = Asf + st * 128 * APITCH;
        float* Bs = Bsf + st * 32 * BPITCH;
#pragma unroll
        for (int l = 0; l < 4; l++) {
            int idx = tid + l * 256;
            int r = idx >> 3;
            int c4 = (idx & 7) << 2;
            cp_async16(&As[r * APITCH + c4], &A[(size_t)(m0 + r) * CC + k0 + c4]);
        }
        constexpr int BC = (32 * BN / 4) / 256;   // f4 chunks per thread (2 or 4)
#pragma unroll
        for (int l = 0; l < BC; l++) {
            int idx = tid + l * 256;
            int r = idx / (BN / 4);
            int cc = (idx % (BN / 4)) << 2;
            const float* Wsrc = (cc < 64) ? W0 : W1;
            int wc = (cc < 64) ? cc : cc - 64;
            cp_async16(&Bs[r * BPITCH + cc], &Wsrc[(size_t)(k0 + r) * HH + wc]);
        }
        cp_commit();
    };

    float c[2][NT][4];
#pragma unroll
    for (int mt = 0; mt < 2; mt++)
#pragma unroll
        for (int nt = 0; nt < NT; nt++)
#pragma unroll
            for (int i = 0; i < 4; i++) c[mt][nt][i] = 0.0f;

    load_tile(0, 0);

    for (int t = 0; t < NK; t++) {
        if (t + 1 < NK) {
            load_tile((t + 1) & 1, (t + 1) * 32);
            asm volatile("cp.async.wait_group 1;\n");
        } else {
            asm volatile("cp.async.wait_group 0;\n");
        }
        __syncthreads();

        const float* As = Asf + (t & 1) * 128 * APITCH;
        const float* Bs = Bsf + (t & 1) * 32 * BPITCH;

#pragma unroll
        for (int ks = 0; ks < 4; ks++) {
            const int kb = ks * 8;
            unsigned af[2][4];
#pragma unroll
            for (int mt = 0; mt < 2; mt++) {
                int r = wm * 32 + mt * 16;
                af[mt][0] = f2tf32(As[(r + g) * APITCH + kb + tig]);
                af[mt][1] = f2tf32(As[(r + g + 8) * APITCH + kb + tig]);
                af[mt][2] = f2tf32(As[(r + g) * APITCH + kb + tig + 4]);
                af[mt][3] = f2tf32(As[(r + g + 8) * APITCH + kb + tig + 4]);
            }
            unsigned bf[NT][2];
#pragma unroll
            for (int nt = 0; nt < NT; nt++) {
                int cb = wn * WN + nt * 8;
                bf[nt][0] = f2tf32(Bs[(kb + tig) * BPITCH + cb + g]);
                bf[nt][1] = f2tf32(Bs[(kb + tig + 4) * BPITCH + cb + g]);
            }
#pragma unroll
            for (int mt = 0; mt < 2; mt++)
#pragma unroll
                for (int nt = 0; nt < NT; nt++) mma_tf32(c[mt][nt], af[mt], bf[nt]);
        }
        __syncthreads();
    }

#pragma unroll
    for (int mt = 0; mt < 2; mt++) {
#pragma unroll
        for (int nt = 0; nt < NT; nt++) {
            int gcol = wn * WN + nt * 8 + 2 * tig;
            float* dst;
            int col;
            if (BN == 64) { dst = C0; col = gcol; }
            else { dst = (gcol < 64) ? C0 : C1; col = (gcol < 64) ? gcol : gcol - 64; }
            int row = m0 + wm * 32 + mt * 16 + g;
            *(float2*)&dst[(size_t)row * HH + col] = make_float2(c[mt][nt][0], c[mt][nt][1]);
            *(float2*)&dst[(size_t)(row + 8) * HH + col] = make_float2(c[mt][nt][2], c[mt][nt][3]);
        }
    }
}

// ---------------------------------------------------------------------------
// Attention v2: one block per batch, 512 threads = 16 warps.
// Each warp handles 4 query rows per sweep (rows base + w + 16m).
// Score: K LDS.128 shared by 4 rows (16 FMA / load).
// PV: p read as broadcast float4 (conflict-free), V scalar conflict-free.
// ---------------------------------------------------------------------------
#define KP 68
#define VP 64
#define QP 68
#define NWARP 16

__global__ __launch_bounds__(512) void attn_kernel(float* __restrict__ out) {
    extern __shared__ float sm[];
    float* Ks = sm;                          // 256*68
    float* Vs = Ks + TT * KP;                // 256*64
    float* qs = Vs + TT * VP;                // 64*68
    float* ws = qs + 64 * QP;                // 16*4*256

    const int b = blockIdx.x;
    const int tid = threadIdx.x;
    const int w = tid >> 5;
    const int lane = tid & 31;

    const float* __restrict__ Kg = g_k + (size_t)b * TT * HH;
    const float* __restrict__ Vg = g_v + (size_t)b * TT * HH;
    const float* __restrict__ Qg = g_q + (size_t)b * TT * HH;
    float* __restrict__ ob = out + (size_t)b * TT * HH;

    // Stage K and V once.
    for (int i = tid; i < TT * 16; i += 512) {
        int r = i >> 4;
        int c4 = (i & 15) << 2;
        *(float4*)&Ks[r * KP + c4] = *(const float4*)&Kg[r * HH + c4];
        *(float4*)&Vs[r * VP + c4] = *(const float4*)&Vg[r * HH + c4];
    }

    const float scale = 0.125f;  // 1/sqrt(64)
    const float NEG = -1e30f;

    for (int it = 0; it < 4; it++) {
        const int base = it * 64;

        // Stage this sweep's 64 q rows (also separates prior sweep's qs reads).
        __syncthreads();
        for (int i = tid; i < 64 * 16; i += 512) {
            int r = i >> 4;
            int c4 = (i & 15) << 2;
            *(float4*)&qs[r * QP + c4] = *(const float4*)&Qg[(base + r) * HH + c4];
        }
        __syncthreads();

        const int jW = (base + w + 48) >> 5;   // max key-group over this warp's rows

        float acc[4][8];
#pragma unroll
        for (int m = 0; m < 4; m++)
#pragma unroll
            for (int j = 0; j < 8; j++) acc[m][j] = 0.0f;

        // ---- Scores: 4 rows share every K load ----
#pragma unroll 4
        for (int h4 = 0; h4 < 16; h4++) {
            float4 qv[4];
#pragma unroll
            for (int m = 0; m < 4; m++) qv[m] = *(float4*)&qs[(w + 16 * m) * QP + h4 * 4];
#pragma unroll
            for (int j = 0; j < 8; j++) {
                if (j <= jW) {
                    int s = lane + (j << 5);
                    float4 k4 = *(float4*)&Ks[s * KP + h4 * 4];
#pragma unroll
                    for (int m = 0; m < 4; m++) {
                        acc[m][j] = fmaf(qv[m].x, k4.x, acc[m][j]);
                        acc[m][j] = fmaf(qv[m].y, k4.y, acc[m][j]);
                        acc[m][j] = fmaf(qv[m].z, k4.z, acc[m][j]);
                        acc[m][j] = fmaf(qv[m].w, k4.w, acc[m][j]);
                    }
                }
            }
        }

        // ---- Softmax per row ----
#pragma unroll
        for (int m = 0; m < 4; m++) {
            const int row = base + w + 16 * m;
            float mx = NEG;
#pragma unroll
            for (int j = 0; j < 8; j++) {
                int s = lane + (j << 5);
                float v = (j <= jW && s <= row) ? acc[m][j] * scale : NEG;
                acc[m][j] = v;
                mx = fmaxf(mx, v);
            }
#pragma unroll
            for (int off = 16; off > 0; off >>= 1)
                mx = fmaxf(mx, __shfl_xor_sync(0xffffffffu, mx, off));
            float sum = 0.0f;
#pragma unroll
            for (int j = 0; j < 8; j++) {
                float p = (acc[m][j] > NEG * 0.5f) ? __expf(acc[m][j] - mx) : 0.0f;
                acc[m][j] = p;
                sum += p;
            }
#pragma unroll
            for (int off = 16; off > 0; off >>= 1)
                sum += __shfl_xor_sync(0xffffffffu, sum, off);
            float inv = __frcp_rn(sum);
#pragma unroll
            for (int j = 0; j < 8; j++) {
                if (j <= jW) ws[(w * 4 + m) * TT + lane + (j << 5)] = acc[m][j] * inv;
            }
        }
        __syncwarp();

        // ---- PV: p broadcast float4, V scalar conflict-free ----
        float o0[4], o1[4];
#pragma unroll
        for (int m = 0; m < 4; m++) { o0[m] = 0.0f; o1[m] = 0.0f; }

        const int smax = base + w + 48;
        for (int s4 = 0; s4 <= smax; s4 += 4) {
            float pm[4][4];
#pragma unroll
            for (int m = 0; m < 4; m++)
                *(float4*)pm[m] = *(float4*)&ws[(w * 4 + m) * TT + s4];
#pragma unroll
            for (int i = 0; i < 4; i++) {
                float va = Vs[(s4 + i) * VP + lane];
                float vb = Vs[(s4 + i) * VP + lane + 32];
#pragma unroll
                for (int m = 0; m < 4; m++) {
                    o0[m] = fmaf(pm[m][i], va, o0[m]);
                    o1[m] = fmaf(pm[m][i], vb, o1[m]);
                }
            }
        }

#pragma unroll
        for (int m = 0; m < 4; m++) {
            const int row = base + w + 16 * m;
            ob[row * HH + lane] = o0[m];
            ob[row * HH + lane + 32] = o1[m];
        }
    }
}

// ---------------------------------------------------------------------------
extern "C" void kernel_launch(void* const* d_in, const int* in_sizes, int n_in,
                              void* d_out, int out_size) {
    const float* x = (const float*)d_in[0];
    const float* y = (const float*)d_in[1];
    const float* Wq = (const float*)d_in[2];
    const float* Wk = (const float*)d_in[3];
    const float* Wv = (const float*)d_in[4];
    float* out = (float*)d_out;

    float* gq;  cudaGetSymbolAddress((void**)&gq, g_q);
    float* gk;  cudaGetSymbolAddress((void**)&gk, g_k);
    float* gv;  cudaGetSymbolAddress((void**)&gv, g_v);

    const int smem_p64 = (2 * 128 * 36 + 2 * 32 * 68) * 4;    // 54272
    const int smem_p128 = (2 * 128 * 36 + 2 * 32 * 132) * 4;  // 70656
    const int smem_attn = (TT * KP + TT * VP + 64 * QP + NWARP * 4 * TT) * 4;  // 218112

    static bool attr_set = false;
    if (!attr_set) {
        cudaFuncSetAttribute(proj_mma_kernel<64>, cudaFuncAttributeMaxDynamicSharedMemorySize, smem_p64);
        cudaFuncSetAttribute(proj_mma_kernel<128>, cudaFuncAttributeMaxDynamicSharedMemorySize, smem_p128);
        cudaFuncSetAttribute(attn_kernel, cudaFuncAttributeMaxDynamicSharedMemorySize, smem_attn);
        attr_set = true;
    }

    // q = x @ Wq  (N=64); [k|v] = y @ [Wk|Wv]  (N=128, y read once)
    proj_mma_kernel<64><<<512, 256, smem_p64>>>(x, Wq, Wq, gq, gq);
    proj_mma_kernel<128><<<512, 256, smem_p128>>>(y, Wk, Wv, gk, gv);

    attn_kernel<<<BB, 512, smem_attn>>>(out);
}

// round 4
// speedup vs baseline: 2.7248x; 1.3130x over previous
#include <cuda_runtime.h>
#include <math.h>
#include <stdint.h>

// Problem shape (fixed)
#define BB 256
#define TT 256
#define CC 512
#define HH 64

// Scratch for projections (device globals: no allocation allowed)
__device__ float g_q[BB * TT * HH];
__device__ float g_k[BB * TT * HH];
__device__ float g_v[BB * TT * HH];

__device__ __forceinline__ unsigned f2tf32(float f) {
    unsigned r;
    asm("cvt.rna.tf32.f32 %0, %1;" : "=r"(r) : "f"(f));
    return r;
}

__device__ __forceinline__ float ex2(float x) {
    float r;
    asm("ex2.approx.ftz.f32 %0, %1;" : "=f"(r) : "f"(x));
    return r;
}

__device__ __forceinline__ void mma_tf32(float c[4], const unsigned a[4], const unsigned b[2]) {
    asm volatile(
        "mma.sync.aligned.m16n8k8.row.col.f32.tf32.tf32.f32 "
        "{%0,%1,%2,%3}, {%4,%5,%6,%7}, {%8,%9}, {%0,%1,%2,%3};\n"
        : "+f"(c[0]), "+f"(c[1]), "+f"(c[2]), "+f"(c[3])
        : "r"(a[0]), "r"(a[1]), "r"(a[2]), "r"(a[3]), "r"(b[0]), "r"(b[1]));
}

__device__ __forceinline__ void cp_async16(void* smem_dst, const void* gmem_src) {
    uint32_t d = (uint32_t)__cvta_generic_to_shared(smem_dst);
    asm volatile("cp.async.cg.shared.global [%0], [%1], 16;\n" :: "r"(d), "l"(gmem_src));
}
__device__ __forceinline__ void cp_commit() { asm volatile("cp.async.commit_group;\n"); }

// ---------------------------------------------------------------------------
// Projection GEMM via tf32 mma.sync + cp.async 2-stage pipeline. (unchanged R3)
// ---------------------------------------------------------------------------
template <int BN>
__global__ __launch_bounds__(256) void proj_mma_kernel(const float* __restrict__ A,
                                                       const float* __restrict__ W0,
                                                       const float* __restrict__ W1,
                                                       float* __restrict__ C0,
                                                       float* __restrict__ C1) {
    constexpr int APITCH = 36;
    constexpr int BPITCH = BN + 4;
    constexpr int WN = BN / 2;
    constexpr int NT = WN / 8;
    constexpr int NK = CC / 32;

    extern __shared__ float smraw[];
    float* Asf = smraw;
    float* Bsf = smraw + 2 * 128 * APITCH;

    const int tid = threadIdx.x;
    const int wid = tid >> 5;
    const int lane = tid & 31;
    const int wm = wid & 3;
    const int wn = wid >> 2;
    const int g = lane >> 2;
    const int tig = lane & 3;
    const int m0 = blockIdx.x * 128;

    auto load_tile = [&](int st, int k0) {
        float* As = Asf + st * 128 * APITCH;
        float* Bs = Bsf + st * 32 * BPITCH;
#pragma unroll
        for (int l = 0; l < 4; l++) {
            int idx = tid + l * 256;
            int r = idx >> 3;
            int c4 = (idx & 7) << 2;
            cp_async16(&As[r * APITCH + c4], &A[(size_t)(m0 + r) * CC + k0 + c4]);
        }
        constexpr int BC = (32 * BN / 4) / 256;
#pragma unroll
        for (int l = 0; l < BC; l++) {
            int idx = tid + l * 256;
            int r = idx / (BN / 4);
            int cc = (idx % (BN / 4)) << 2;
            const float* Wsrc = (cc < 64) ? W0 : W1;
            int wc = (cc < 64) ? cc : cc - 64;
            cp_async16(&Bs[r * BPITCH + cc], &Wsrc[(size_t)(k0 + r) * HH + wc]);
        }
        cp_commit();
    };

    float c[2][NT][4];
#pragma unroll
    for (int mt = 0; mt < 2; mt++)
#pragma unroll
        for (int nt = 0; nt < NT; nt++)
#pragma unroll
            for (int i = 0; i < 4; i++) c[mt][nt][i] = 0.0f;

    load_tile(0, 0);

    for (int t = 0; t < NK; t++) {
        if (t + 1 < NK) {
            load_tile((t + 1) & 1, (t + 1) * 32);
            asm volatile("cp.async.wait_group 1;\n");
        } else {
            asm volatile("cp.async.wait_group 0;\n");
        }
        __syncthreads();

        const float* As = Asf + (t & 1) * 128 * APITCH;
        const float* Bs = Bsf + (t & 1) * 32 * BPITCH;

#pragma unroll
        for (int ks = 0; ks < 4; ks++) {
            const int kb = ks * 8;
            unsigned af[2][4];
#pragma unroll
            for (int mt = 0; mt < 2; mt++) {
                int r = wm * 32 + mt * 16;
                af[mt][0] = f2tf32(As[(r + g) * APITCH + kb + tig]);
                af[mt][1] = f2tf32(As[(r + g + 8) * APITCH + kb + tig]);
                af[mt][2] = f2tf32(As[(r + g) * APITCH + kb + tig + 4]);
                af[mt][3] = f2tf32(As[(r + g + 8) * APITCH + kb + tig + 4]);
            }
            unsigned bf[NT][2];
#pragma unroll
            for (int nt = 0; nt < NT; nt++) {
                int cb = wn * WN + nt * 8;
                bf[nt][0] = f2tf32(Bs[(kb + tig) * BPITCH + cb + g]);
                bf[nt][1] = f2tf32(Bs[(kb + tig + 4) * BPITCH + cb + g]);
            }
#pragma unroll
            for (int mt = 0; mt < 2; mt++)
#pragma unroll
                for (int nt = 0; nt < NT; nt++) mma_tf32(c[mt][nt], af[mt], bf[nt]);
        }
        __syncthreads();
    }

#pragma unroll
    for (int mt = 0; mt < 2; mt++) {
#pragma unroll
        for (int nt = 0; nt < NT; nt++) {
            int gcol = wn * WN + nt * 8 + 2 * tig;
            float* dst;
            int col;
            if (BN == 64) { dst = C0; col = gcol; }
            else { dst = (gcol < 64) ? C0 : C1; col = (gcol < 64) ? gcol : gcol - 64; }
            int row = m0 + wm * 32 + mt * 16 + g;
            *(float2*)&dst[(size_t)row * HH + col] = make_float2(c[mt][nt][0], c[mt][nt][1]);
            *(float2*)&dst[(size_t)(row + 8) * HH + col] = make_float2(c[mt][nt][2], c[mt][nt][3]);
        }
    }
}

// ---------------------------------------------------------------------------
// Flash attention with tf32 mma.sync.
// Grid: 512 blocks (2 per batch). Block: 256 threads = 8 warps.
// Each warp: 16 query rows. Online softmax over 64-key chunks.
// ---------------------------------------------------------------------------
#define KP 68   // K pitch:  b-frag banks (s0+cb+g)*68 + kb+tig -> 4g+tig unique
#define VP 72   // V pitch:  b-frag banks (s0+kb+tig)*72 + h0+g -> 8tig+g unique
#define QP 68   // Q pitch:  a-frag banks 4g+tig unique
#define PP 68   // P pitch:  a-frag banks 4g+tig unique

__global__ __launch_bounds__(256) void attn_kernel(float* __restrict__ out) {
    extern __shared__ float sm[];
    float* Ks = sm;                          // 256*68
    float* Vs = Ks + TT * KP;                // 256*72
    float* Qs = Vs + TT * VP;                // 128*68
    float* Ps = Qs + 128 * QP;               // 8*16*68

    const int bx = blockIdx.x;
    const int b = bx >> 1;
    const int q0 = (bx & 1) * 128;
    const int tid = threadIdx.x;
    const int w = tid >> 5;
    const int lane = tid & 31;
    const int g = lane >> 2;
    const int tig = lane & 3;

    const float* __restrict__ Kg = g_k + (size_t)b * TT * HH;
    const float* __restrict__ Vg = g_v + (size_t)b * TT * HH;
    const float* __restrict__ Qg = g_q + (size_t)b * TT * HH;
    float* __restrict__ ob = out + (size_t)b * TT * HH;

    // ---- Stage K, V (full) and Q (this block's 128 rows) ----
    for (int i = tid; i < TT * 16; i += 256) {
        int r = i >> 4;
        int c4 = (i & 15) << 2;
        *(float4*)&Ks[r * KP + c4] = *(const float4*)&Kg[r * HH + c4];
        *(float4*)&Vs[r * VP + c4] = *(const float4*)&Vg[r * HH + c4];
    }
    for (int i = tid; i < 128 * 16; i += 256) {
        int r = i >> 4;
        int c4 = (i & 15) << 2;
        *(float4*)&Qs[r * QP + c4] = *(const float4*)&Qg[(q0 + r) * HH + c4];
    }
    __syncthreads();

    const int qr0 = w * 16;          // warp's local query-row base
    const int r0 = q0 + qr0;         // global query-row base
    const int rg0 = r0 + g;          // thread row 0
    const int rg1 = r0 + g + 8;      // thread row 1
    float* Pw = Ps + w * 16 * PP;

    const float c2 = 0.125f * 1.44269504089f;  // scale * log2(e)

    float o[8][4];
#pragma unroll
    for (int nt = 0; nt < 8; nt++)
#pragma unroll
        for (int j = 0; j < 4; j++) o[nt][j] = 0.0f;

    float mt0 = -1e30f, mt1 = -1e30f;  // running max (log2-scaled units)
    float l0 = 0.0f, l1 = 0.0f;        // running partial sums (this thread's cols)

    const int cmax = (r0 + 15) >> 6;

    for (int ch = 0; ch <= cmax; ch++) {
        const int s0 = ch * 64;

        // ---- Scores: S[16 x 64] = Q_tile @ K_chunk^T ----
        float sc[8][4];
#pragma unroll
        for (int nt = 0; nt < 8; nt++)
#pragma unroll
            for (int j = 0; j < 4; j++) sc[nt][j] = 0.0f;

#pragma unroll
        for (int kc = 0; kc < 8; kc++) {
            const int kb = kc * 8;
            unsigned a[4];
            a[0] = f2tf32(Qs[(qr0 + g) * QP + kb + tig]);
            a[1] = f2tf32(Qs[(qr0 + g + 8) * QP + kb + tig]);
            a[2] = f2tf32(Qs[(qr0 + g) * QP + kb + tig + 4]);
            a[3] = f2tf32(Qs[(qr0 + g + 8) * QP + kb + tig + 4]);
#pragma unroll
            for (int nt = 0; nt < 8; nt++) {
                unsigned bfr[2];
                int krow = s0 + nt * 8 + g;
                bfr[0] = f2tf32(Ks[krow * KP + kb + tig]);
                bfr[1] = f2tf32(Ks[krow * KP + kb + tig + 4]);
                mma_tf32(sc[nt], a, bfr);
            }
        }

        // ---- Mask + online softmax (log2 domain) ----
        float cm0 = -1e30f, cm1 = -1e30f;
#pragma unroll
        for (int nt = 0; nt < 8; nt++) {
            const int colb = s0 + nt * 8 + 2 * tig;
            float t0a = (colb <= rg0) ? sc[nt][0] * c2 : -1e30f;
            float t0b = (colb + 1 <= rg0) ? sc[nt][1] * c2 : -1e30f;
            float t1a = (colb <= rg1) ? sc[nt][2] * c2 : -1e30f;
            float t1b = (colb + 1 <= rg1) ? sc[nt][3] * c2 : -1e30f;
            sc[nt][0] = t0a; sc[nt][1] = t0b; sc[nt][2] = t1a; sc[nt][3] = t1b;
            cm0 = fmaxf(cm0, fmaxf(t0a, t0b));
            cm1 = fmaxf(cm1, fmaxf(t1a, t1b));
        }
        cm0 = fmaxf(cm0, __shfl_xor_sync(0xffffffffu, cm0, 1));
        cm0 = fmaxf(cm0, __shfl_xor_sync(0xffffffffu, cm0, 2));
        cm1 = fmaxf(cm1, __shfl_xor_sync(0xffffffffu, cm1, 1));
        cm1 = fmaxf(cm1, __shfl_xor_sync(0xffffffffu, cm1, 2));

        const float nm0 = fmaxf(mt0, cm0);
        const float nm1 = fmaxf(mt1, cm1);
        const float f0 = ex2(mt0 - nm0);
        const float f1 = ex2(mt1 - nm1);
        mt0 = nm0; mt1 = nm1;
        l0 *= f0; l1 *= f1;

        __syncwarp();
#pragma unroll
        for (int nt = 0; nt < 8; nt++) {
            float p0 = ex2(sc[nt][0] - nm0);
            float p1 = ex2(sc[nt][1] - nm0);
            float p2 = ex2(sc[nt][2] - nm1);
            float p3 = ex2(sc[nt][3] - nm1);
            l0 += p0 + p1;
            l1 += p2 + p3;
            // rescale O accumulators
            o[nt][0] *= f0; o[nt][1] *= f0; o[nt][2] *= f1; o[nt][3] *= f1;
            // store P (pre-converted to tf32 bits) for the PV mma
            int cb = nt * 8 + 2 * tig;
            *(float2*)&Pw[g * PP + cb] =
                make_float2(__uint_as_float(f2tf32(p0)), __uint_as_float(f2tf32(p1)));
            *(float2*)&Pw[(g + 8) * PP + cb] =
                make_float2(__uint_as_float(f2tf32(p2)), __uint_as_float(f2tf32(p3)));
        }
        __syncwarp();

        // ---- PV: O += P_chunk @ V_chunk ----
#pragma unroll
        for (int kc = 0; kc < 8; kc++) {
            const int kb = kc * 8;
            unsigned a[4];
            a[0] = __float_as_uint(Pw[g * PP + kb + tig]);
            a[1] = __float_as_uint(Pw[(g + 8) * PP + kb + tig]);
            a[2] = __float_as_uint(Pw[g * PP + kb + tig + 4]);
            a[3] = __float_as_uint(Pw[(g + 8) * PP + kb + tig + 4]);
            const int vr0 = s0 + kb + tig;
            const int vr1 = s0 + kb + tig + 4;
#pragma unroll
            for (int nt = 0; nt < 8; nt++) {
                unsigned bfr[2];
                bfr[0] = f2tf32(Vs[vr0 * VP + nt * 8 + g]);
                bfr[1] = f2tf32(Vs[vr1 * VP + nt * 8 + g]);
                mma_tf32(o[nt], a, bfr);
            }
        }
    }

    // ---- Normalize and write out ----
    l0 += __shfl_xor_sync(0xffffffffu, l0, 1);
    l0 += __shfl_xor_sync(0xffffffffu, l0, 2);
    l1 += __shfl_xor_sync(0xffffffffu, l1, 1);
    l1 += __shfl_xor_sync(0xffffffffu, l1, 2);
    const float inv0 = __frcp_rn(l0);
    const float inv1 = __frcp_rn(l1);

#pragma unroll
    for (int nt = 0; nt < 8; nt++) {
        int cb = nt * 8 + 2 * tig;
        *(float2*)&ob[(size_t)rg0 * HH + cb] = make_float2(o[nt][0] * inv0, o[nt][1] * inv0);
        *(float2*)&ob[(size_t)rg1 * HH + cb] = make_float2(o[nt][2] * inv1, o[nt][3] * inv1);
    }
}

// ---------------------------------------------------------------------------
extern "C" void kernel_launch(void* const* d_in, const int* in_sizes, int n_in,
                              void* d_out, int out_size) {
    const float* x = (const float*)d_in[0];
    const float* y = (const float*)d_in[1];
    const float* Wq = (const float*)d_in[2];
    const float* Wk = (const float*)d_in[3];
    const float* Wv = (const float*)d_in[4];
    float* out = (float*)d_out;

    float* gq;  cudaGetSymbolAddress((void**)&gq, g_q);
    float* gk;  cudaGetSymbolAddress((void**)&gk, g_k);
    float* gv;  cudaGetSymbolAddress((void**)&gv, g_v);

    const int smem_p64 = (2 * 128 * 36 + 2 * 32 * 68) * 4;
    const int smem_p128 = (2 * 128 * 36 + 2 * 32 * 132) * 4;
    const int smem_attn = (TT * KP + TT * VP + 128 * QP + 8 * 16 * PP) * 4;  // 212992

    static bool attr_set = false;
    if (!attr_set) {
        cudaFuncSetAttribute(proj_mma_kernel<64>, cudaFuncAttributeMaxDynamicSharedMemorySize, smem_p64);
        cudaFuncSetAttribute(proj_mma_kernel<128>, cudaFuncAttributeMaxDynamicSharedMemorySize, smem_p128);
        cudaFuncSetAttribute(attn_kernel, cudaFuncAttributeMaxDynamicSharedMemorySize, smem_attn);
        attr_set = true;
    }

    // q = x @ Wq  (N=64); [k|v] = y @ [Wk|Wv]  (N=128, y read once)
    proj_mma_kernel<64><<<512, 256, smem_p64>>>(x, Wq, Wq, gq, gq);
    proj_mma_kernel<128><<<512, 256, smem_p128>>>(y, Wk, Wv, gk, gv);

    attn_kernel<<<2 * BB, 256, smem_attn>>>(out);
}

// round 5
// speedup vs baseline: 3.5107x; 1.2884x over previous
#include <cuda_runtime.h>
#include <math.h>
#include <stdint.h>

// Problem shape (fixed)
#define BB 256
#define TT 256
#define CC 512
#define HH 64

// Scratch for projections (device globals: no allocation allowed)
__device__ float g_q[BB * TT * HH];
__device__ float g_k[BB * TT * HH];
__device__ float g_v[BB * TT * HH];

__device__ __forceinline__ unsigned f2tf32(float f) {
    unsigned r;
    asm("cvt.rna.tf32.f32 %0, %1;" : "=r"(r) : "f"(f));
    return r;
}

__device__ __forceinline__ float ex2(float x) {
    float r;
    asm("ex2.approx.ftz.f32 %0, %1;" : "=f"(r) : "f"(x));
    return r;
}

__device__ __forceinline__ void mma_tf32(float c[4], const unsigned a[4], const unsigned b[2]) {
    asm volatile(
        "mma.sync.aligned.m16n8k8.row.col.f32.tf32.tf32.f32 "
        "{%0,%1,%2,%3}, {%4,%5,%6,%7}, {%8,%9}, {%0,%1,%2,%3};\n"
        : "+f"(c[0]), "+f"(c[1]), "+f"(c[2]), "+f"(c[3])
        : "r"(a[0]), "r"(a[1]), "r"(a[2]), "r"(a[3]), "r"(b[0]), "r"(b[1]));
}

__device__ __forceinline__ void cp_async16(void* smem_dst, const void* gmem_src) {
    uint32_t d = (uint32_t)__cvta_generic_to_shared(smem_dst);
    asm volatile("cp.async.cg.shared.global [%0], [%1], 16;\n" :: "r"(d), "l"(gmem_src));
}
__device__ __forceinline__ void cp_commit() { asm volatile("cp.async.commit_group;\n"); }

// ---------------------------------------------------------------------------
// Projection GEMM body (tf32 mma.sync + cp.async 2-stage). Same math as R3/R4.
// ---------------------------------------------------------------------------
template <int BN>
__device__ __forceinline__ void proj_body(const float* __restrict__ A,
                                          const float* __restrict__ W0,
                                          const float* __restrict__ W1,
                                          float* __restrict__ C0,
                                          float* __restrict__ C1,
                                          int blk) {
    constexpr int APITCH = 36;
    constexpr int BPITCH = BN + 4;
    constexpr int WN = BN / 2;
    constexpr int NT = WN / 8;
    constexpr int NK = CC / 32;

    extern __shared__ float smraw[];
    float* Asf = smraw;
    float* Bsf = smraw + 2 * 128 * APITCH;

    const int tid = threadIdx.x;
    const int wid = tid >> 5;
    const int lane = tid & 31;
    const int wm = wid & 3;
    const int wn = wid >> 2;
    const int g = lane >> 2;
    const int tig = lane & 3;
    const int m0 = blk * 128;

    auto load_tile = [&](int st, int k0) {
        float* As = Asf + st * 128 * APITCH;
        float* Bs = Bsf + st * 32 * BPITCH;
#pragma unroll
        for (int l = 0; l < 4; l++) {
            int idx = tid + l * 256;
            int r = idx >> 3;
            int c4 = (idx & 7) << 2;
            cp_async16(&As[r * APITCH + c4], &A[(size_t)(m0 + r) * CC + k0 + c4]);
        }
        constexpr int BC = (32 * BN / 4) / 256;
#pragma unroll
        for (int l = 0; l < BC; l++) {
            int idx = tid + l * 256;
            int r = idx / (BN / 4);
            int cc = (idx % (BN / 4)) << 2;
            const float* Wsrc = (cc < 64) ? W0 : W1;
            int wc = (cc < 64) ? cc : cc - 64;
            cp_async16(&Bs[r * BPITCH + cc], &Wsrc[(size_t)(k0 + r) * HH + wc]);
        }
        cp_commit();
    };

    float c[2][NT][4];
#pragma unroll
    for (int mt = 0; mt < 2; mt++)
#pragma unroll
        for (int nt = 0; nt < NT; nt++)
#pragma unroll
            for (int i = 0; i < 4; i++) c[mt][nt][i] = 0.0f;

    load_tile(0, 0);

    for (int t = 0; t < NK; t++) {
        if (t + 1 < NK) {
            load_tile((t + 1) & 1, (t + 1) * 32);
            asm volatile("cp.async.wait_group 1;\n");
        } else {
            asm volatile("cp.async.wait_group 0;\n");
        }
        __syncthreads();

        const float* As = Asf + (t & 1) * 128 * APITCH;
        const float* Bs = Bsf + (t & 1) * 32 * BPITCH;

#pragma unroll
        for (int ks = 0; ks < 4; ks++) {
            const int kb = ks * 8;
            unsigned af[2][4];
#pragma unroll
            for (int mt = 0; mt < 2; mt++) {
                int r = wm * 32 + mt * 16;
                af[mt][0] = f2tf32(As[(r + g) * APITCH + kb + tig]);
                af[mt][1] = f2tf32(As[(r + g + 8) * APITCH + kb + tig]);
                af[mt][2] = f2tf32(As[(r + g) * APITCH + kb + tig + 4]);
                af[mt][3] = f2tf32(As[(r + g + 8) * APITCH + kb + tig + 4]);
            }
            unsigned bf[NT][2];
#pragma unroll
            for (int nt = 0; nt < NT; nt++) {
                int cb = wn * WN + nt * 8;
                bf[nt][0] = f2tf32(Bs[(kb + tig) * BPITCH + cb + g]);
                bf[nt][1] = f2tf32(Bs[(kb + tig + 4) * BPITCH + cb + g]);
            }
#pragma unroll
            for (int mt = 0; mt < 2; mt++)
#pragma unroll
                for (int nt = 0; nt < NT; nt++) mma_tf32(c[mt][nt], af[mt], bf[nt]);
        }
        __syncthreads();
    }

#pragma unroll
    for (int mt = 0; mt < 2; mt++) {
#pragma unroll
        for (int nt = 0; nt < NT; nt++) {
            int gcol = wn * WN + nt * 8 + 2 * tig;
            float* dst;
            int col;
            if (BN == 64) { dst = C0; col = gcol; }
            else { dst = (gcol < 64) ? C0 : C1; col = (gcol < 64) ? gcol : gcol - 64; }
            int row = m0 + wm * 32 + mt * 16 + g;
            *(float2*)&dst[(size_t)row * HH + col] = make_float2(c[mt][nt][0], c[mt][nt][1]);
            *(float2*)&dst[(size_t)(row + 8) * HH + col] = make_float2(c[mt][nt][2], c[mt][nt][3]);
        }
    }
}

// Merged launch: blocks [0,512) do q = x@Wq; blocks [512,1024) do [k|v] = y@[Wk|Wv].
__global__ __launch_bounds__(256) void proj_all_kernel(const float* __restrict__ x,
                                                       const float* __restrict__ y,
                                                       const float* __restrict__ Wq,
                                                       const float* __restrict__ Wk,
                                                       const float* __restrict__ Wv,
                                                       float* __restrict__ gq,
                                                       float* __restrict__ gk,
                                                       float* __restrict__ gv) {
    if (blockIdx.x < 512) proj_body<64>(x, Wq, Wq, gq, gq, blockIdx.x);
    else                  proj_body<128>(y, Wk, Wv, gk, gv, blockIdx.x - 512);
}

// ---------------------------------------------------------------------------
// Flash attention, tf32 mma.sync, chunked K/V with cp.async double buffer.
// Grid: 512 blocks (2 per batch), 256 threads = 8 warps x 16 query rows.
// smem 104 KB -> 2 CTAs/SM. Q fragments live in registers.
// ---------------------------------------------------------------------------
#define KP 68   // K pitch: b-frag bank = 4g+tig (unique)
#define VP 72   // V pitch: b-frag bank = 8tig+g (unique)
#define PP 68   // P pitch: a-frag bank = 4g+tig (unique)
#define CHK 64  // keys per chunk

__global__ __launch_bounds__(256, 2) void attn_kernel(float* __restrict__ out) {
    extern __shared__ float sm[];
    float* Ks = sm;                          // 2 * 64 * KP
    float* Vs = Ks + 2 * CHK * KP;           // 2 * 64 * VP
    float* Ps = Vs + 2 * CHK * VP;           // 8 * 16 * PP

    const int bx = blockIdx.x;
    const int b = bx >> 1;
    const int q0 = (bx & 1) * 128;
    const int tid = threadIdx.x;
    const int w = tid >> 5;
    const int lane = tid & 31;
    const int g = lane >> 2;
    const int tig = lane & 3;

    const float* __restrict__ Kg = g_k + (size_t)b * TT * HH;
    const float* __restrict__ Vg = g_v + (size_t)b * TT * HH;
    const float* __restrict__ Qg = g_q + (size_t)b * TT * HH;
    float* __restrict__ ob = out + (size_t)b * TT * HH;

    auto stage_load = [&](int ch) {
        float* Kc = Ks + (ch & 1) * CHK * KP;
        float* Vc = Vs + (ch & 1) * CHK * VP;
        const int s0 = ch * CHK;
#pragma unroll
        for (int l = 0; l < 4; l++) {
            int idx = tid + l * 256;
            int r = idx >> 4;
            int c4 = (idx & 15) << 2;
            cp_async16(&Kc[r * KP + c4], &Kg[(size_t)(s0 + r) * HH + c4]);
            cp_async16(&Vc[r * VP + c4], &Vg[(size_t)(s0 + r) * HH + c4]);
        }
        cp_commit();
    };

    stage_load(0);

    // ---- Preload Q fragments into registers (one-time, overlaps cp.async) ----
    const int r0 = q0 + w * 16;       // warp's global query-row base
    const int rg0 = r0 + g;
    const int rg1 = r0 + g + 8;
    unsigned qf[8][4];
#pragma unroll
    for (int kc = 0; kc < 8; kc++) {
        const int kb = kc * 8;
        qf[kc][0] = f2tf32(Qg[(size_t)rg0 * HH + kb + tig]);
        qf[kc][1] = f2tf32(Qg[(size_t)rg1 * HH + kb + tig]);
        qf[kc][2] = f2tf32(Qg[(size_t)rg0 * HH + kb + tig + 4]);
        qf[kc][3] = f2tf32(Qg[(size_t)rg1 * HH + kb + tig + 4]);
    }

    float* Pw = Ps + w * 16 * PP;
    const float c2 = 0.125f * 1.44269504089f;  // scale * log2(e)

    float o[8][4];
#pragma unroll
    for (int nt = 0; nt < 8; nt++)
#pragma unroll
        for (int j = 0; j < 4; j++) o[nt][j] = 0.0f;

    float mt0 = -1e30f, mt1 = -1e30f;
    float l0 = 0.0f, l1 = 0.0f;

    const int CB = (q0 + 127) >> 6;   // block's last chunk (1 or 3)
    const int cw = (r0 + 15) >> 6;    // warp's last chunk

    for (int ch = 0; ch <= CB; ch++) {
        asm volatile("cp.async.wait_group 0;\n");
        __syncthreads();
        if (ch < CB) stage_load(ch + 1);

        // Convert this chunk's K/V to tf32 in place (once per element).
        {
            float* Kc = Ks + (ch & 1) * CHK * KP;
            float* Vc = Vs + (ch & 1) * CHK * VP;
#pragma unroll
            for (int l = 0; l < 4; l++) {
                int idx = tid + l * 256;
                int r = idx >> 4;
                int c4 = (idx & 15) << 2;
                float4 kv = *(float4*)&Kc[r * KP + c4];
                kv.x = __uint_as_float(f2tf32(kv.x));
                kv.y = __uint_as_float(f2tf32(kv.y));
                kv.z = __uint_as_float(f2tf32(kv.z));
                kv.w = __uint_as_float(f2tf32(kv.w));
                *(float4*)&Kc[r * KP + c4] = kv;
                float4 vv = *(float4*)&Vc[r * VP + c4];
                vv.x = __uint_as_float(f2tf32(vv.x));
                vv.y = __uint_as_float(f2tf32(vv.y));
                vv.z = __uint_as_float(f2tf32(vv.z));
                vv.w = __uint_as_float(f2tf32(vv.w));
                *(float4*)&Vc[r * VP + c4] = vv;
            }
        }
        __syncthreads();

        if (ch > cw) continue;   // this warp's rows don't reach this chunk

        const float* Kc = Ks + (ch & 1) * CHK * KP;
        const float* Vc = Vs + (ch & 1) * CHK * VP;
        const int s0 = ch * CHK;
        const int ntmax = min(7, (r0 + 15 - s0) >> 3);  // last key-tile with any valid col
        const bool full = (s0 + CHK - 1 <= r0);          // no masking needed

        // ---- Scores ----
        float sc[8][4];
#pragma unroll
        for (int nt = 0; nt < 8; nt++)
            if (nt <= ntmax) { sc[nt][0] = 0; sc[nt][1] = 0; sc[nt][2] = 0; sc[nt][3] = 0; }
#pragma unroll
        for (int kc = 0; kc < 8; kc++) {
            const int kb = kc * 8;
#pragma unroll
            for (int nt = 0; nt < 8; nt++) {
                if (nt <= ntmax) {
                    unsigned bfr[2];
                    int krow = nt * 8 + g;
                    bfr[0] = __float_as_uint(Kc[krow * KP + kb + tig]);
                    bfr[1] = __float_as_uint(Kc[krow * KP + kb + tig + 4]);
                    mma_tf32(sc[nt], qf[kc], bfr);
                }
            }
        }

        // ---- Mask + online softmax (log2 domain) ----
        float cm0 = -1e30f, cm1 = -1e30f;
#pragma unroll
        for (int nt = 0; nt < 8; nt++) {
            if (nt <= ntmax) {
                if (full) {
                    sc[nt][0] *= c2; sc[nt][1] *= c2; sc[nt][2] *= c2; sc[nt][3] *= c2;
                } else {
                    const int colb = s0 + nt * 8 + 2 * tig;
                    sc[nt][0] = (colb <= rg0) ? sc[nt][0] * c2 : -1e30f;
                    sc[nt][1] = (colb + 1 <= rg0) ? sc[nt][1] * c2 : -1e30f;
                    sc[nt][2] = (colb <= rg1) ? sc[nt][2] * c2 : -1e30f;
                    sc[nt][3] = (colb + 1 <= rg1) ? sc[nt][3] * c2 : -1e30f;
                }
                cm0 = fmaxf(cm0, fmaxf(sc[nt][0], sc[nt][1]));
                cm1 = fmaxf(cm1, fmaxf(sc[nt][2], sc[nt][3]));
            }
        }
        cm0 = fmaxf(cm0, __shfl_xor_sync(0xffffffffu, cm0, 1));
        cm0 = fmaxf(cm0, __shfl_xor_sync(0xffffffffu, cm0, 2));
        cm1 = fmaxf(cm1, __shfl_xor_sync(0xffffffffu, cm1, 1));
        cm1 = fmaxf(cm1, __shfl_xor_sync(0xffffffffu, cm1, 2));

        const float nm0 = fmaxf(mt0, cm0);
        const float nm1 = fmaxf(mt1, cm1);
        const float f0 = ex2(mt0 - nm0);
        const float f1 = ex2(mt1 - nm1);
        mt0 = nm0; mt1 = nm1;
        l0 *= f0; l1 *= f1;
#pragma unroll
        for (int nt = 0; nt < 8; nt++) {
            o[nt][0] *= f0; o[nt][1] *= f0; o[nt][2] *= f1; o[nt][3] *= f1;
        }

        __syncwarp();
#pragma unroll
        for (int nt = 0; nt < 8; nt++) {
            if (nt <= ntmax) {
                float p0 = ex2(sc[nt][0] - nm0);
                float p1 = ex2(sc[nt][1] - nm0);
                float p2 = ex2(sc[nt][2] - nm1);
                float p3 = ex2(sc[nt][3] - nm1);
                l0 += p0 + p1;
                l1 += p2 + p3;
                int cb = nt * 8 + 2 * tig;
                *(float2*)&Pw[g * PP + cb] =
                    make_float2(__uint_as_float(f2tf32(p0)), __uint_as_float(f2tf32(p1)));
                *(float2*)&Pw[(g + 8) * PP + cb] =
                    make_float2(__uint_as_float(f2tf32(p2)), __uint_as_float(f2tf32(p3)));
            }
        }
        __syncwarp();

        // ---- PV: O += P @ V_chunk  (kc beyond ntmax has P == 0, skipped) ----
#pragma unroll
        for (int kc = 0; kc < 8; kc++) {
            if (kc <= ntmax) {
                const int kb = kc * 8;
                unsigned a[4];
                a[0] = __float_as_uint(Pw[g * PP + kb + tig]);
                a[1] = __float_as_uint(Pw[(g + 8) * PP + kb + tig]);
                a[2] = __float_as_uint(Pw[g * PP + kb + tig + 4]);
                a[3] = __float_as_uint(Pw[(g + 8) * PP + kb + tig + 4]);
                const int vr0 = kb + tig;
                const int vr1 = kb + tig + 4;
#pragma unroll
                for (int nt = 0; nt < 8; nt++) {
                    unsigned bfr[2];
                    bfr[0] = __float_as_uint(Vc[vr0 * VP + nt * 8 + g]);
                    bfr[1] = __float_as_uint(Vc[vr1 * VP + nt * 8 + g]);
                    mma_tf32(o[nt], a, bfr);
                }
            }
        }
    }

    // ---- Normalize and write out ----
    l0 += __shfl_xor_sync(0xffffffffu, l0, 1);
    l0 += __shfl_xor_sync(0xffffffffu, l0, 2);
    l1 += __shfl_xor_sync(0xffffffffu, l1, 1);
    l1 += __shfl_xor_sync(0xffffffffu, l1, 2);
    const float inv0 = __frcp_rn(l0);
    const float inv1 = __frcp_rn(l1);

#pragma unroll
    for (int nt = 0; nt < 8; nt++) {
        int cb = nt * 8 + 2 * tig;
        *(float2*)&ob[(size_t)rg0 * HH + cb] = make_float2(o[nt][0] * inv0, o[nt][1] * inv0);
        *(float2*)&ob[(size_t)rg1 * HH + cb] = make_float2(o[nt][2] * inv1, o[nt][3] * inv1);
    }
}

// ---------------------------------------------------------------------------
extern "C" void kernel_launch(void* const* d_in, const int* in_sizes, int n_in,
                              void* d_out, int out_size) {
    const float* x = (const float*)d_in[0];
    const float* y = (const float*)d_in[1];
    const float* Wq = (const float*)d_in[2];
    const float* Wk = (const float*)d_in[3];
    const float* Wv = (const float*)d_in[4];
    float* out = (float*)d_out;

    float* gq;  cudaGetSymbolAddress((void**)&gq, g_q);
    float* gk;  cudaGetSymbolAddress((void**)&gk, g_k);
    float* gv;  cudaGetSymbolAddress((void**)&gv, g_v);

    const int smem_proj = (2 * 128 * 36 + 2 * 32 * 132) * 4;                   // 70656
    const int smem_attn = (2 * CHK * KP + 2 * CHK * VP + 8 * 16 * PP) * 4;     // 106496

    static bool attr_set = false;
    if (!attr_set) {
        cudaFuncSetAttribute(proj_all_kernel, cudaFuncAttributeMaxDynamicSharedMemorySize, smem_proj);
        cudaFuncSetAttribute(attn_kernel, cudaFuncAttributeMaxDynamicSharedMemorySize, smem_attn);
        attr_set = true;
    }

    proj_all_kernel<<<1024, 256, smem_proj>>>(x, y, Wq, Wk, Wv, gq, gk, gv);
    attn_kernel<<<2 * BB, 256, smem_attn>>>(out);
}